// round 9
// baseline (speedup 1.0000x reference)
#include <cuda_runtime.h>
#include <math.h>

#define NB 8       // batch
#define NS 5       // max slabs reachable (spans in [0,5])
#define NSFULL 6   // slab dimension of the input tensor
#define NM 64      // M
#define NV 32000   // vocab
#define NT 8       // template length
#define VSPLIT 8
#define CHUNK  (NV / VSPLIT)   // 4000 floats
#define CHUNK4 (CHUNK / 4)     // 1000 float4
#define NITER  ((CHUNK4 + 127) / 128)   // 8
#define SSTRIDE4 ((NM * NV) / 4)        // float4 stride between slabs
#define NBLK   1024                     // all co-resident (128 thr, <=7/SM)
#define NPAIR  (NB / 2)                 // 4 batch pairs
#define TILES  1024                     // tiles per phase: 2b x 64m x 8chunk

// tiny scratch (__device__ globals, no runtime allocation)
__device__ float    g_pmax[NB * NT * NM * VSPLIT];  // per-chunk partial max
__device__ float    g_out0[NB * NT * NM];           // out[b,t,m,0] (+pad)
__device__ unsigned g_count;                        // barrier arrivals (self-resets)
__device__ unsigned g_sense;                        // barrier sense (monotonic)
__device__ unsigned g_ctrA[NPAIR];                  // A-phase tile tickets
__device__ unsigned g_ctrC[NPAIR];                  // C-phase tile tickets

// ---------------------------------------------------------------------------
// Grid-wide barrier (all NBLK blocks co-resident). Sense monotonic
// (replay-safe); count self-resets.
// ---------------------------------------------------------------------------
__device__ __forceinline__ void grid_barrier() {
    __syncthreads();
    __threadfence();
    if (threadIdx.x == 0) {
        const unsigned s0 = *(volatile unsigned*)&g_sense;
        const unsigned v  = atomicAdd(&g_count, 1);
        if (v == NBLK - 1) {
            g_count = 0;
            __threadfence();
            atomicAdd(&g_sense, 1);
        } else {
            while (*(volatile unsigned*)&g_sense == s0) { __nanosleep(64); }
        }
    }
    __syncthreads();
    __threadfence();
}

// ---------------------------------------------------------------------------
// Phase A body, compile-time S.
// ---------------------------------------------------------------------------
template <int S>
__device__ __forceinline__ void phase_a_body(
    const float4* __restrict__ p0, int b, int m, int chunk,
    const float (&sw)[NT][NS], const float (&sw0)[NT], float (&maxv)[NT]) {

    const int tid = threadIdx.x;
    #pragma unroll
    for (int t = 0; t < NT; t++) maxv[t] = -INFINITY;

    #pragma unroll 2
    for (int j = 0; j < NITER; j++) {
        const int i = tid + j * 128;
        if (i < CHUNK4) {
            float4 x[S > 0 ? S : 1];
            #pragma unroll
            for (int s = 0; s < S; s++) x[s] = p0[i + s * SSTRIDE4];

            #pragma unroll
            for (int t = 0; t < NT; t++) {
                float ax = 0.f, ay = 0.f, az = 0.f, aw = 0.f;
                #pragma unroll
                for (int s = 0; s < S; s++) {
                    const float wv = sw[t][s];
                    ax = fmaf(wv, x[s].x, ax);
                    ay = fmaf(wv, x[s].y, ay);
                    az = fmaf(wv, x[s].z, az);
                    aw = fmaf(wv, x[s].w, aw);
                }
                maxv[t] = fmaxf(maxv[t], fmaxf(fmaxf(ax, ay), fmaxf(az, aw)));
            }
        }
    }

    // cold epilogue: out[b,t,m,0] (dot + pad one-hot), chunk 0 / thread 0 only
    if (chunk == 0 && tid == 0) {
        float x0[S > 0 ? S : 1];
        #pragma unroll
        for (int s = 0; s < S; s++)
            x0[s] = reinterpret_cast<const float*>(p0 + s * SSTRIDE4)[0];
        #pragma unroll
        for (int t = 0; t < NT; t++) {
            float v = 0.f;
            #pragma unroll
            for (int s = 0; s < S; s++) v = fmaf(sw[t][s], x0[s], v);
            if (m == 0) v += sw0[t];
            g_out0[((size_t)b * NT + t) * NM + m] = v;
        }
    }
}

// ---------------------------------------------------------------------------
// Phase C body, compile-time S, streaming stores.
// ---------------------------------------------------------------------------
template <int S>
__device__ __forceinline__ void phase_c_body(
    const float4* __restrict__ p0, float4* __restrict__ dst,
    const float (&ws)[NS], float w0, int ml, int chunk) {

    const int tid = threadIdx.x;
    #pragma unroll 2
    for (int j = 0; j < NITER; j++) {
        const int i = tid + j * 128;
        if (i < CHUNK4) {
            float4 x[S > 0 ? S : 1];
            #pragma unroll
            for (int s = 0; s < S; s++) x[s] = p0[i + s * SSTRIDE4];

            float4 acc = make_float4(0.f, 0.f, 0.f, 0.f);
            #pragma unroll
            for (int s = 0; s < S; s++) {
                const float wv = ws[s];
                acc.x = fmaf(wv, x[s].x, acc.x);
                acc.y = fmaf(wv, x[s].y, acc.y);
                acc.z = fmaf(wv, x[s].z, acc.z);
                acc.w = fmaf(wv, x[s].w, acc.w);
            }
            if (chunk == 0 && i == 0 && ml == 0) acc.x += w0;  // pad one-hot
            __stcs(dst + i, acc);
        }
    }
}

// ---------------------------------------------------------------------------
// Fused persistent kernel with dynamic tile queues.
// argmax==0  <=>  out[v=0] attains the max (argmax ties go to index 0)
// ---------------------------------------------------------------------------
__global__ void __launch_bounds__(128, 7)
fused_kernel(const float* __restrict__ in, const float* __restrict__ tmpl,
             const int* __restrict__ spans, float* __restrict__ out) {
    const int tid = threadIdx.x;

    __shared__ int s_ticket;
    __shared__ int s_cached_b;          // batch whose srow map is in smem
    __shared__ float spart[4][NT];
    __shared__ unsigned char sflags[NT * NM];
    __shared__ unsigned char slen[NT];
    __shared__ short         srow[NM];

    if (tid == 0) s_cached_b = -1;

    int   cur_b = -1;                   // batch whose A-weights are in regs
    int   S = 0;
    float sw[NT][NS], sw0[NT];

    for (int p = 0; p < NPAIR; p++) {
        // ================= phase A: dynamic tiles =================
        for (;;) {
            __syncthreads();                       // protect spart reuse
            if (tid == 0) s_ticket = (int)atomicAdd(&g_ctrA[p], 1u);
            __syncthreads();
            const int tk = s_ticket;
            if (tk >= TILES) break;

            const int b     = 2 * p + (tk >> 9);
            const int rem   = tk & 511;
            const int m     = rem >> 3;
            const int chunk = rem & 7;

            if (b != cur_b) {                      // uniform across block
                cur_b = b;
                S = __ldg(&spans[b]);
                #pragma unroll
                for (int t = 0; t < NT; t++) {
                    sw0[t] = __ldg(&tmpl[((size_t)b * NT + t) * (NSFULL + 1)]);
                    #pragma unroll
                    for (int s = 0; s < NS; s++)
                        sw[t][s] = __ldg(&tmpl[((size_t)b * NT + t) * (NSFULL + 1) + s + 1]);
                }
            }

            const float4* pa = reinterpret_cast<const float4*>(
                in + ((size_t)b * NSFULL * NM + m) * NV + chunk * CHUNK);

            float maxv[NT];
            switch (S) {
                case 0: phase_a_body<0>(pa, b, m, chunk, sw, sw0, maxv); break;
                case 1: phase_a_body<1>(pa, b, m, chunk, sw, sw0, maxv); break;
                case 2: phase_a_body<2>(pa, b, m, chunk, sw, sw0, maxv); break;
                case 3: phase_a_body<3>(pa, b, m, chunk, sw, sw0, maxv); break;
                case 4: phase_a_body<4>(pa, b, m, chunk, sw, sw0, maxv); break;
                default: phase_a_body<5>(pa, b, m, chunk, sw, sw0, maxv); break;
            }

            #pragma unroll
            for (int t = 0; t < NT; t++) {
                float v = maxv[t];
                #pragma unroll
                for (int off = 16; off > 0; off >>= 1)
                    v = fmaxf(v, __shfl_xor_sync(0xFFFFFFFFu, v, off));
                maxv[t] = v;
            }
            const int warp = tid >> 5, lane = tid & 31;
            if (lane == 0) {
                #pragma unroll
                for (int t = 0; t < NT; t++) spart[warp][t] = maxv[t];
            }
            __syncthreads();
            if (tid < NT) {
                const int t = tid;
                float mx = fmaxf(fmaxf(spart[0][t], spart[1][t]),
                                 fmaxf(spart[2][t], spart[3][t]));
                g_pmax[(((size_t)b * NT + t) * NM + m) * VSPLIT + chunk] = mx;
            }
        }

        // all A_p results visible before any C_p scan
        grid_barrier();

        // ================= phase C: dynamic tiles =================
        for (;;) {
            __syncthreads();                       // protect srow/sflags reuse
            if (tid == 0) s_ticket = (int)atomicAdd(&g_ctrC[p], 1u);
            __syncthreads();
            const int tk = s_ticket;
            if (tk >= TILES) break;

            const int b     = 2 * p + (tk >> 9);
            const int rem   = tk & 511;
            const int jrow  = rem >> 3;
            const int chunk = rem & 7;

            if (s_cached_b != b) {                 // uniform; rebuild scan map
                #pragma unroll
                for (int k = 0; k < 4; k++) {
                    const int tm  = tid + 128 * k;           // t*64 + mm
                    const int idx = b * NT * NM + tm;
                    const float4* pm = reinterpret_cast<const float4*>(
                        &g_pmax[(size_t)idx * VSPLIT]);
                    const float4 a = __ldcg(pm), c = __ldcg(pm + 1);
                    float mx = fmaxf(fmaxf(fmaxf(a.x, a.y), fmaxf(a.z, a.w)),
                                     fmaxf(fmaxf(c.x, c.y), fmaxf(c.z, c.w)));
                    sflags[tm] = (__ldcg(&g_out0[idx]) >= mx) ? 1 : 0;
                }
                __syncthreads();
                if (tid < NT) {
                    int len = NM;
                    for (int mm = 0; mm < NM; mm++)
                        if (sflags[tid * NM + mm]) { len = mm; break; }
                    slen[tid] = (unsigned char)len;
                }
                __syncthreads();
                if (tid == 0) {
                    for (int q = 0; q < NM; q++) srow[q] = -1;
                    int idx = 0;
                    for (int t = 0; t < NT; t++) {
                        int len = slen[t];
                        if (len > NM - idx) len = NM - idx;
                        for (int k = 0; k < len; k++)
                            srow[idx + k] = (short)((t << 8) | k);
                        idx += len;
                    }
                    s_cached_b = b;
                }
                __syncthreads();
            }

            float4* dst = reinterpret_cast<float4*>(
                out + ((size_t)b * NM + jrow) * NV + chunk * CHUNK);
            const int code = srow[jrow];

            if (code < 0) {
                const float4 z = make_float4(0.f, 0.f, 0.f, 0.f);
                #pragma unroll 2
                for (int jj = 0; jj < NITER; jj++) {
                    const int i = tid + jj * 128;
                    if (i < CHUNK4) __stcs(dst + i, z);
                }
            } else {
                const int t  = code >> 8;
                const int ml = code & 255;
                const int Sc = __ldg(&spans[b]);

                float ws[NS];
                #pragma unroll
                for (int s = 0; s < NS; s++)
                    ws[s] = __ldg(&tmpl[((size_t)b * NT + t) * (NSFULL + 1) + s + 1]);
                const float w0 = __ldg(&tmpl[((size_t)b * NT + t) * (NSFULL + 1)]);

                const float4* pc = reinterpret_cast<const float4*>(
                    in + ((size_t)b * NSFULL * NM + ml) * NV + chunk * CHUNK);

                switch (Sc) {
                    case 0: phase_c_body<0>(pc, dst, ws, w0, ml, chunk); break;
                    case 1: phase_c_body<1>(pc, dst, ws, w0, ml, chunk); break;
                    case 2: phase_c_body<2>(pc, dst, ws, w0, ml, chunk); break;
                    case 3: phase_c_body<3>(pc, dst, ws, w0, ml, chunk); break;
                    case 4: phase_c_body<4>(pc, dst, ws, w0, ml, chunk); break;
                    default: phase_c_body<5>(pc, dst, ws, w0, ml, chunk); break;
                }
            }
        }
        // no barrier before next A: scratch indices disjoint across pairs.
    }

    // ---- final: last-arriving block resets queue counters (replay-safe).
    // All queue atomics happen-before this arrive; no spin needed.
    __syncthreads();
    if (tid == 0) {
        if (atomicAdd(&g_count, 1) == NBLK - 1) {
            g_count = 0;
            #pragma unroll
            for (int i = 0; i < NPAIR; i++) { g_ctrA[i] = 0; g_ctrC[i] = 0; }
            __threadfence();
        }
    }
}

// ---------------------------------------------------------------------------
extern "C" void kernel_launch(void* const* d_in, const int* in_sizes, int n_in,
                              void* d_out, int out_size) {
    const float* in    = (const float*)d_in[0];  // [8,6,64,32000] f32
    const float* tmpl  = (const float*)d_in[1];  // [8,8,7] f32
    const int*   spans = (const int*)d_in[2];    // [8] i32
    float*       out   = (float*)d_out;          // [8,64,32000] f32

    fused_kernel<<<NBLK, 128>>>(in, tmpl, spans, out);
}